// round 9
// baseline (speedup 1.0000x reference)
#include <cuda_runtime.h>
#include <cstdint>

// ---------------------------------------------------------------------------
// Exact integer replication of the reference gate-level fp32 adder circuit.
// Words in IEEE layout: bit31=sign, [30:23]=exp, [22:0]=mant.
// Matches the circuit, NOT IEEE (truncated subnormals, subnormal mantissa path
// takes top 23 bits unshifted, big-diff at ediff>=24, exact cancel -> +0,
// overflow checked on computed_e pre-cancel).
// ---------------------------------------------------------------------------
__device__ __forceinline__ uint32_t fpadd_circuit(uint32_t ua, uint32_t ub) {
    uint32_t sa = ua >> 31, sb = ub >> 31;
    uint32_t ea = (ua >> 23) & 0xFFu, eb = (ub >> 23) & 0xFFu;
    uint32_t ma = ua & 0x7FFFFFu, mb = ub & 0x7FFFFFu;

    uint32_t ha = (ea != 0u) ? 1u : 0u;
    uint32_t hb = (eb != 0u) ? 1u : 0u;
    uint32_t eaf = ha ? ea : 1u;
    uint32_t ebf = hb ? eb : 1u;

    uint32_t Ma = (ha << 27) | (ma << 4);
    uint32_t Mb = (hb << 27) | (mb << 4);
    uint32_t maga = (ha << 23) | ma;
    uint32_t magb = (hb << 23) | mb;

    bool exp_eq = (eaf == ebf);
    bool a_ge_b = (eaf > ebf) || (exp_eq && (maga >= magb));
    bool abs_eq = exp_eq && (maga == magb);

    uint32_t ediff = a_ge_b ? (eaf - ebf) : (ebf - eaf);
    bool big = (ediff >= 24u);

    uint32_t e_max  = a_ge_b ? eaf : ebf;
    uint32_t Ml     = a_ge_b ? Ma  : Mb;
    uint32_t Ms0    = a_ge_b ? Mb  : Ma;

    uint32_t Ms;
    bool shift_sticky;
    if (big) {
        Ms = 0u;
        shift_sticky = (Ms0 != 0u);
    } else {
        Ms = Ms0 >> ediff;
        shift_sticky = (Ms0 & ((1u << ediff) - 1u)) != 0u;
    }

    bool dsign = (sa != sb);
    uint32_t s_large = a_ge_b ? sa : sb;

    uint32_t mant_res, carry;
    if (dsign) {
        mant_res = (Ml - Ms - (shift_sticky ? 1u : 0u)) & 0x0FFFFFFFu;
        carry = 0u;
    } else {
        uint32_t s = Ml + Ms;
        carry = s >> 28;
        mant_res = s & 0x0FFFFFFFu;
    }

    uint32_t lzc = mant_res ? (uint32_t)(__clz(mant_res) - 4) : 28u;
    bool underflow = (lzc >= e_max);
    uint32_t norm = (mant_res << lzc) & 0x0FFFFFFFu;

    uint32_t e_after = (e_max - lzc) & 0xFFu;
    uint32_t e_normal = underflow ? 0u : e_after;
    uint32_t final_e_pre = carry ? ((e_max + 1u) & 0xFFu) : e_normal;

    uint32_t m_pre, r_pre;
    bool st_pre;
    if (carry) {
        m_pre  = mant_res >> 5;
        r_pre  = (mant_res >> 4) & 1u;
        st_pre = (mant_res & 0xFu) != 0u;
    } else {
        m_pre  = (norm >> 4) & 0x7FFFFFu;
        r_pre  = (norm >> 3) & 1u;
        st_pre = (norm & 0x7u) != 0u;
    }
    st_pre = st_pre || shift_sticky;

    uint32_t m_sel = underflow ? (mant_res >> 5) : m_pre;
    bool do_round = (r_pre != 0u) && (st_pre || ((m_sel & 1u) != 0u)) && !underflow;

    uint32_t m24 = m_sel + (do_round ? 1u : 0u);
    uint32_t rc = (m24 >> 23) & 1u;
    uint32_t m_final = m24 & 0x7FFFFFu;
    uint32_t computed_e = (final_e_pre + rc) & 0xFFu;

    bool cancel = dsign && abs_eq;
    uint32_t out_s = cancel ? 0u : s_large;
    uint32_t out_e = cancel ? 0u : computed_e;
    uint32_t out_m = cancel ? 0u : m_final;

    bool ea1 = (ea == 0xFFu), eb1 = (eb == 0xFFu);
    bool manz = (ma != 0u),   mbnz = (mb != 0u);
    bool a_inf = ea1 && !manz, b_inf = eb1 && !mbnz;
    bool any_nan = (ea1 && manz) || (eb1 && mbnz);
    bool res_nan = any_nan || (dsign && a_inf && b_inf);
    bool ovf = (computed_e == 0xFFu);

    uint32_t out = (out_s << 31) | (out_e << 23) | out_m;
    if (a_inf || b_inf || ovf) out = (s_large << 31) | 0x7F800000u;
    if (res_nan)               out = 0x7FFFFFFFu;
    return out;
}

#define RPB     128        // rows per tile (== threads per block)
#define SROWW   36         // smem WORDS per row: 32 data + 4 pad (144B; quarter-
                           // wavefront LDS.128 banks t*4 mod 32 -> conflict-free)
#define STAGE_W (RPB * SROWW)          // 4608 words per input array per stage
#define SMEM_BYTES (2 * 2 * STAGE_W * 4)   // 2 stages x {A,B} = 73728 B

__device__ __forceinline__ void cpasync16(uint32_t saddr, const void* gptr) {
    asm volatile("cp.async.cg.shared.global [%0], [%1], 16;" :: "r"(saddr), "l"(gptr));
}

// 4 floats (0.0/1.0 words) -> 4-bit nibble, element0 = MSB of the nibble
__device__ __forceinline__ uint32_t nib4(uint4 v) {
    uint32_t s0 = __byte_perm(v.x, v.y, 0x0073);        // b0=x.b3, b1=y.b3
    uint32_t s1 = __byte_perm(v.z, v.w, 0x0073);
    uint32_t pk = __byte_perm(s0, s1, 0x5410) & 0x01010101u;
    return (pk * 0x08040201u) >> 24;                    // x<<3|y<<2|z<<1|w
}

__device__ __forceinline__ void issue_tile_copy(uint32_t* smem_base, int stage,
                                                const uint4* A4, const uint4* B4,
                                                int tile, int tid) {
    uint32_t* sA = smem_base + (size_t)stage * 2 * STAGE_W;
    uint32_t* sB = sA + STAGE_W;
    const uint4* Af = A4 + (size_t)tile * RPB * 8;
    const uint4* Bf = B4 + (size_t)tile * RPB * 8;
    const uint32_t saA = (uint32_t)__cvta_generic_to_shared(sA);
    const uint32_t saB = (uint32_t)__cvta_generic_to_shared(sB);
    #pragma unroll
    for (int it = 0; it < 8; ++it) {
        int v = it * RPB + tid;                      // uint4 chunk index in tile
        uint32_t off = (uint32_t)(v >> 3) * (SROWW * 4) + (uint32_t)(v & 7) * 16;
        cpasync16(saA + off, Af + v);
        cpasync16(saB + off, Bf + v);
    }
    asm volatile("cp.async.commit_group;");
}

__device__ __forceinline__ void compute_store_tile(const uint32_t* smem_base, int stage,
                                                   uint32_t* O, int tile, int tid) {
    const uint32_t* sA = smem_base + (size_t)stage * 2 * STAGE_W;
    const uint32_t* sB = sA + STAGE_W;
    const int row0 = tile * RPB;

    // phase 2: read own row (8x LDS.128 per input), pack, run circuit
    const uint4* ra = (const uint4*)(sA + tid * SROWW);
    const uint4* rb = (const uint4*)(sB + tid * SROWW);
    uint32_t ua = 0u, ub = 0u;
    #pragma unroll
    for (int k = 0; k < 8; ++k) {
        ua |= nib4(ra[k]) << (28 - 4 * k);
        ub |= nib4(rb[k]) << (28 - 4 * k);
    }
    uint32_t res = fpadd_circuit(ua, ub);

    // phase 3: shfl scatter, coalesced 16B stores
    const int lane  = tid & 31;
    const int wrow0 = row0 + (tid & ~31);
    const int sub   = lane >> 3;
    const uint32_t e0 = (lane & 7) << 2;
    #pragma unroll
    for (int k = 0; k < 8; ++k) {
        int idx  = (k << 2) + sub;
        uint32_t w = __shfl_sync(0xFFFFFFFFu, res, idx);
        uint4 o;
        o.x = (uint32_t)(((int32_t)(w << (e0 + 0))) >> 31) & 0x3F800000u;
        o.y = (uint32_t)(((int32_t)(w << (e0 + 1))) >> 31) & 0x3F800000u;
        o.z = (uint32_t)(((int32_t)(w << (e0 + 2))) >> 31) & 0x3F800000u;
        o.w = (uint32_t)(((int32_t)(w << (e0 + 3))) >> 31) & 0x3F800000u;
        *(uint4*)(O + (size_t)(wrow0 + idx) * 32 + e0) = o;
    }
}

__global__ void __launch_bounds__(128)
spike_fp32_adder_kernel(const uint4* __restrict__ A4,
                        const uint4* __restrict__ B4,
                        uint32_t* __restrict__ O,
                        int nrows, int ntiles) {
    extern __shared__ __align__(16) uint32_t smem[];
    const int tid = threadIdx.x;
    const int stride = gridDim.x;

    // ---- tail rows (nrows % RPB), handled by block 0, scalar path ----
    if (blockIdx.x == 0) {
        int r = ntiles * RPB + tid;
        if (r < nrows) {
            const uint4* Ar = A4 + (size_t)r * 8;
            const uint4* Br = B4 + (size_t)r * 8;
            uint32_t ua = 0u, ub = 0u;
            #pragma unroll
            for (int k = 0; k < 8; ++k) {
                ua |= nib4(Ar[k]) << (28 - 4 * k);
                ub |= nib4(Br[k]) << (28 - 4 * k);
            }
            uint32_t w = fpadd_circuit(ua, ub);
            #pragma unroll
            for (int k = 0; k < 8; ++k) {
                uint4 o;
                uint32_t e0 = k << 2;
                o.x = (uint32_t)(((int32_t)(w << (e0 + 0))) >> 31) & 0x3F800000u;
                o.y = (uint32_t)(((int32_t)(w << (e0 + 1))) >> 31) & 0x3F800000u;
                o.z = (uint32_t)(((int32_t)(w << (e0 + 2))) >> 31) & 0x3F800000u;
                o.w = (uint32_t)(((int32_t)(w << (e0 + 3))) >> 31) & 0x3F800000u;
                *(uint4*)(O + (size_t)r * 32 + e0) = o;
            }
        }
    }

    // ---- pipelined full tiles: 2-stage cp.async ring ----
    int tile = blockIdx.x;
    if (tile >= ntiles) return;

    issue_tile_copy(smem, 0, A4, B4, tile, tid);

    int i = 0;
    for (; tile < ntiles; tile += stride, ++i) {
        int next = tile + stride;
        if (next < ntiles) {
            issue_tile_copy(smem, (i + 1) & 1, A4, B4, next, tid);
            asm volatile("cp.async.wait_group 1;");
        } else {
            asm volatile("cp.async.wait_group 0;");
        }
        __syncthreads();                      // all threads' copies visible
        compute_store_tile(smem, i & 1, O, tile, tid);
        __syncthreads();                      // done reading before stage reuse
    }
}

extern "C" void kernel_launch(void* const* d_in, const int* in_sizes, int n_in,
                              void* d_out, int out_size) {
    const uint4* A = (const uint4*)d_in[0];
    const uint4* B = (const uint4*)d_in[1];
    uint32_t* O = (uint32_t*)d_out;

    int nrows  = in_sizes[0] / 32;            // 524288
    int ntiles = nrows / RPB;                 // 4096 full tiles
    int blocks = 444;                         // 3 x 148 SMs: one exact wave
    if (ntiles > 0 && ntiles < blocks) blocks = ntiles;
    if (blocks == 0) blocks = 1;              // tail-only degenerate case

    cudaFuncSetAttribute(spike_fp32_adder_kernel,
                         cudaFuncAttributeMaxDynamicSharedMemorySize, SMEM_BYTES);
    spike_fp32_adder_kernel<<<blocks, RPB, SMEM_BYTES>>>(A, B, O, nrows, ntiles);
}